// round 17
// baseline (speedup 1.0000x reference)
#include <cuda_runtime.h>

#define KSEL 512
#define NBINS 4096                // 12-bit histogram (sign+exp+3 mantissa bits)
#define SHIFT1 20
#define BCAP 4096                 // smem boundary cache in K2 (expected m ~ 145)
#define NBLK3 128                 // main-compute blocks
#define BLOCK3 512
#define NGROUP 64                 // 64 groups of 8 negs
#define LN2_F 0.69314718055994530942

__device__ unsigned int g_hist[NBINS];   // zero-init; re-zeroed by K3 each run
__device__ float g_E[KSEL];
__device__ float g_partials[NBLK3];
__device__ int g_ticket = 0;

__device__ __forceinline__ unsigned int f2key(float x) {
    unsigned int u = __float_as_uint(x);
    return (u & 0x80000000u) ? ~u : (u | 0x80000000u);  // order-preserving
}
__device__ __forceinline__ float key2f(unsigned int k) {
    unsigned int u = (k & 0x80000000u) ? (k ^ 0x80000000u) : ~k;
    return __uint_as_float(u);
}

// Blackwell packed f32x2 (PTX-only)
__device__ __forceinline__ unsigned long long ffma2(unsigned long long a,
                                                    unsigned long long b,
                                                    unsigned long long c) {
    unsigned long long d;
    asm("fma.rn.f32x2 %0, %1, %2, %3;" : "=l"(d) : "l"(a), "l"(b), "l"(c));
    return d;
}
__device__ __forceinline__ unsigned long long pack2(float lo, float hi) {
    unsigned long long d;
    asm("mov.b64 %0, {%1, %2};" : "=l"(d) : "f"(lo), "f"(hi));
    return d;
}
__device__ __forceinline__ void unpack2(unsigned long long v, float& lo, float& hi) {
    asm("mov.b64 {%0, %1}, %2;" : "=f"(lo), "=f"(hi) : "l"(v));
}

// ===========================================================================
// K1: global histogram (1 key per thread, spread REDG atomics)
// ===========================================================================
__global__ void __launch_bounds__(512, 1)
k1_hist(const float* __restrict__ neg, int n_neg)
{
    const int idx = blockIdx.x * 512 + threadIdx.x;
    if (idx < n_neg)
        atomicAdd(&g_hist[f2key(__ldg(&neg[idx])) >> SHIFT1], 1u);
}

// ===========================================================================
// K2: single block — scan hist, classify all keys, resolve boundary -> g_E
// ===========================================================================
__global__ void __launch_bounds__(1024, 1)
k2_select(const float* __restrict__ neg, int n_neg)
{
    __shared__ unsigned int hist[NBINS];                 // 16 KB
    __shared__ unsigned int sbound[BCAP];                // 16 KB
    __shared__ unsigned int sh_chunk, sh_exclc, sh_bstar, sh_C1, sh_rem;
    __shared__ unsigned int sh_c1, sh_cb;

    const int tid = threadIdx.x;
    const int lane = tid & 31;

    // load own keys up-front (full MLP, L2-hot after K1)
    unsigned int keys[16];
    #pragma unroll
    for (int c = 0; c < 16; c++) {
        const int idx = c * 1024 + tid;
        keys[c] = (idx < n_neg) ? f2key(__ldg(&neg[idx])) : 0u;
    }

    for (int j = tid; j < NBINS; j += 1024) hist[j] = g_hist[j];
    if (tid == 0) { sh_c1 = 0u; sh_cb = 0u; }
    __syncthreads();

    // two-level warp scan (warp 0) for exact threshold bin
    if (tid < 32) {
        unsigned int sum = 0u;
        #pragma unroll
        for (int j = 0; j < NBINS / 32; j++) sum += hist[tid * (NBINS / 32) + j];
        unsigned int incl = sum;
        #pragma unroll
        for (int off = 1; off < 32; off <<= 1) {
            const unsigned int v = __shfl_down_sync(0xffffffffu, incl, off);
            if (tid + off < 32) incl += v;
        }
        const unsigned int excl = incl - sum;
        if (excl < KSEL && KSEL <= incl) { sh_chunk = (unsigned int)tid; sh_exclc = excl; }
        __syncwarp();
        const unsigned int c = sh_chunk, exclc = sh_exclc;
        const int base = (int)c * (NBINS / 32) + tid * 4;
        unsigned int s2 = hist[base] + hist[base + 1] + hist[base + 2] + hist[base + 3];
        unsigned int incl2 = s2;
        #pragma unroll
        for (int off = 1; off < 32; off <<= 1) {
            const unsigned int v = __shfl_down_sync(0xffffffffu, incl2, off);
            if (tid + off < 32) incl2 += v;
        }
        const unsigned int above = exclc + (incl2 - s2);
        if (above < KSEL && KSEL <= above + s2) {        // exactly one lane
            unsigned int cum = above;
            #pragma unroll
            for (int j = 3; j >= 0; j--) {
                const unsigned int nb = hist[base + j];
                if (cum + nb >= KSEL) {
                    sh_bstar = (unsigned int)(base + j);
                    sh_C1 = cum;  sh_rem = KSEL - cum;
                    break;
                }
                cum += nb;
            }
        }
    }
    __syncthreads();
    const unsigned int bs = sh_bstar, C1 = sh_C1, rem = sh_rem;

    // classify: winners -> g_E (any order), boundary bin -> smem
    #pragma unroll
    for (int c = 0; c < 16; c++) {
        const unsigned int k = keys[c];
        const bool in = (c * 1024 + tid) < n_neg;
        const unsigned int bin = k >> SHIFT1;
        const bool gt = in && (bin > bs);
        const bool eq = in && (bin == bs);
        const unsigned int bgt = __ballot_sync(0xffffffffu, gt);
        const unsigned int beq = __ballot_sync(0xffffffffu, eq);
        if (bgt) {
            const int leader = __ffs(bgt) - 1;
            unsigned int base;
            if (lane == leader) base = atomicAdd(&sh_c1, (unsigned int)__popc(bgt));
            base = __shfl_sync(0xffffffffu, base, leader);
            if (gt) g_E[base + __popc(bgt & ((1u << lane) - 1u))] = __expf(key2f(k));
        }
        if (beq) {
            const int leader = __ffs(beq) - 1;
            unsigned int base;
            if (lane == leader) base = atomicAdd(&sh_cb, (unsigned int)__popc(beq));
            base = __shfl_sync(0xffffffffu, base, leader);
            if (eq) {
                const unsigned int x = base + __popc(beq & ((1u << lane) - 1u));
                if (x < BCAP) sbound[x] = k;             // m ~ 145 expected
            }
        }
    }
    __syncthreads();

    // boundary bin: O(m^2) exact rank over a total order (ties bit-identical)
    const unsigned int m = min(sh_cb, (unsigned int)BCAP);
    for (unsigned int bi = tid; bi < m; bi += 1024) {
        const unsigned int k = sbound[bi];
        unsigned int rank = 0u;
        for (unsigned int j = 0; j < m; j++) {
            const unsigned int kj = sbound[j];
            rank += (kj > k) || (kj == k && j < bi);
        }
        if (rank < rem) g_E[C1 + rank] = __expf(key2f(k));
    }
}

// ===========================================================================
// K3: main compute — symmetric-poly coeffs + packed Horner + reduction
// ===========================================================================
__global__ void __launch_bounds__(BLOCK3, 1)
k3_main(const float* __restrict__ pos, int n_pos,
        float* __restrict__ out, float final_scale, int rpb)
{
    __shared__ float sE[KSEL] __attribute__((aligned(16)));
    __shared__ unsigned long long sC[NGROUP][9];         // packed-dup coeffs
    __shared__ float sFs[64];
    __shared__ float sh_red[BLOCK3 / 32];
    __shared__ int sh_last;

    const int tid = threadIdx.x;
    const int lane = tid & 31;
    const int b = blockIdx.x;

    sE[tid] = g_E[tid];                                  // L2 broadcast (2 KB)
    if (tid < NBINS / NBLK3)                             // re-zero hist for replay
        g_hist[b * (NBINS / NBLK3) + tid] = 0u;
    if (tid < rpb) {                                     // F once per row (64 MUFU)
        const int row = b * rpb + tid;
        sFs[tid] = (row < n_pos) ? __expf(-__ldg(&pos[row])) : 0.0f;
    }
    __syncthreads();

    // per-group elementary symmetric coefficients: prod(1+E_j x) = sum e_k x^k
    if (tid < NGROUP) {
        float c[9];
        c[0] = 1.0f;
        #pragma unroll
        for (int k = 1; k < 9; k++) c[k] = 0.0f;
        #pragma unroll
        for (int j = 0; j < 8; j++) {
            const float e = sE[tid * 8 + j];
            #pragma unroll
            for (int k = 8; k >= 1; k--) c[k] = __fmaf_rn(e, c[k - 1], c[k]);
        }
        #pragma unroll
        for (int k = 0; k < 9; k++) sC[tid][k] = pack2(c[k], c[k]);
    }
    __syncthreads();

    // Horner over 4 groups per thread, 2 rows packed per lane-pair
    const int rp = tid >> 4;                             // row-pair 0..31
    const int c4 = tid & 15;
    const unsigned long long FF = pack2(sFs[rp], sFs[rp + 32]);
    float acc = 0.0f;                                    // accumulates log2
    #pragma unroll
    for (int gi = 0; gi < 4; gi++) {
        const int g = c4 + 16 * gi;
        unsigned long long p = sC[g][8];
        #pragma unroll
        for (int k = 7; k >= 0; k--)
            p = ffma2(p, FF, sC[g][k]);                  // P(F) = prod(1+E F)
        float plo, phi;
        unpack2(p, plo, phi);                            // <= ~1.4e28: no overflow
        acc += __log2f(plo);
        acc += __log2f(phi);
    }

    // deterministic block reduction + last-block finalize
    #pragma unroll
    for (int off = 16; off > 0; off >>= 1)
        acc += __shfl_down_sync(0xffffffffu, acc, off);
    if (lane == 0) sh_red[tid >> 5] = acc;
    __syncthreads();
    if (tid == 0) {
        float a = 0.0f;
        #pragma unroll
        for (int w = 0; w < BLOCK3 / 32; w++) a += sh_red[w];
        g_partials[b] = a;
        __threadfence();                                 // release partial
        sh_last = (atomicAdd(&g_ticket, 1) == NBLK3 - 1) ? 1 : 0;
    }
    __syncthreads();
    if (sh_last) {
        if (tid == 0) __threadfence();                   // acquire partials
        __syncthreads();
        if (tid < 32) {
            float a = 0.0f;
            #pragma unroll
            for (int j = 0; j < NBLK3 / 32; j++) a += g_partials[j * 32 + tid];
            #pragma unroll
            for (int off = 16; off > 0; off >>= 1)
                a += __shfl_down_sync(0xffffffffu, a, off);
            if (tid == 0) {
                out[0] = a * final_scale;                // ln2 * inv_denom
                g_ticket = 0;                            // reset for replay
            }
        }
    }
}

// ---------------------------------------------------------------------------
extern "C" void kernel_launch(void* const* d_in, const int* in_sizes, int n_in,
                              void* d_out, int out_size) {
    const float* neg = (const float*)d_in[0];   // score_neg [16384]
    const float* pos = (const float*)d_in[1];   // score_pos [8192]
    const int n_neg = in_sizes[0];
    const int n_pos = in_sizes[1];

    const int rpb = (n_pos + NBLK3 - 1) / NBLK3;            // 64 rows per block
    const float final_scale =
        (float)(LN2_F / ((double)n_neg * (double)n_pos));   // ln2 * inv_denom

    k1_hist<<<(n_neg + 511) / 512, 512>>>(neg, n_neg);
    k2_select<<<1, 1024>>>(neg, n_neg);
    k3_main<<<NBLK3, BLOCK3>>>(pos, n_pos, (float*)d_out, final_scale, rpb);
}